// round 13
// baseline (speedup 1.0000x reference)
#include <cuda_runtime.h>

#define Nn    6000
#define DEG   16
#define Mm    17          // DEG + 1
#define NT    16
#define MTt   10
#define NF    128
#define KT    160         // NT * MTt
#define PT    12          // padded per-template chunk
#define TKSTR 204         // per-k T region stride (17 rows x 12)
#define NITER 10
#define THREADS 256       // 8 warps; warp w owns k = 2w, 2w+1
#define GEMM_ROWS 40
#define GEMM_SMEM ((KT * 129 + GEMM_ROWS * NF) * 4)

__device__ float g_G[Nn * KT];
__device__ float g_f2n[KT];

// ---------------------------------------------------------------------------
// packed f32x2 helpers (sm_103a)
// ---------------------------------------------------------------------------
typedef unsigned long long ull;
__device__ __forceinline__ ull pk2(float lo, float hi) {
    ull r;
    asm("mov.b64 %0, {%1, %2};" : "=l"(r) : "f"(lo), "f"(hi));
    return r;
}
__device__ __forceinline__ void upk2(float& lo, float& hi, ull v) {
    asm("mov.b64 {%0, %1}, %2;" : "=f"(lo), "=f"(hi) : "l"(v));
}
__device__ __forceinline__ void ffma2(ull& d, ull a, ull b) {
    asm("fma.rn.f32x2 %0, %1, %2, %0;" : "+l"(d) : "l"(a), "l"(b));
}
__device__ __forceinline__ ull fma2r(ull a, ull b, ull c) {
    ull d;
    asm("fma.rn.f32x2 %0, %1, %2, %3;" : "=l"(d) : "l"(a), "l"(b), "l"(c));
    return d;
}
__device__ __forceinline__ ull mul2r(ull a, ull b) {
    ull d;
    asm("mul.rn.f32x2 %0, %1, %2;" : "=l"(d) : "l"(a), "l"(b));
    return d;
}
__device__ __forceinline__ float hadd2(ull v) {
    float lo, hi; upk2(lo, hi, v);
    return lo + hi;
}
__device__ __forceinline__ void ld_chunk(ull* v, const float* p) {
    float4 a = *(const float4*)p, b = *(const float4*)(p + 4),
           c = *(const float4*)(p + 8);
    v[0] = pk2(a.x, a.y); v[1] = pk2(a.z, a.w);
    v[2] = pk2(b.x, b.y); v[3] = pk2(b.z, b.w);
    v[4] = pk2(c.x, c.y);
}
__device__ __forceinline__ void lt_update(ull* ltp, const ull* McBp,
                                          const ull* ccp, const ull* y2p,
                                          ull cA2p, ull ncA4p, ull neg1p) {
    #pragma unroll
    for (int j = 0; j < 5; j++) {
        ull d = fma2r(cA2p, ccp[j], McBp[j]);
        d = fma2r(ncA4p, y2p[j], d);
        ltp[j] = fma2r(d, neg1p, ltp[j]);
    }
}
// softmax over 10 packed values -> T row (scaled 1/17); stores 10 floats only
__device__ __forceinline__ void softmax_store(const ull* ltp, float* dstRow) {
    float e[10];
    #pragma unroll
    for (int j = 0; j < 5; j++) upk2(e[2*j], e[2*j+1], ltp[j]);
    float mx = e[0];
    #pragma unroll
    for (int t = 1; t < MTt; t++) mx = fmaxf(mx, e[t]);
    float ssum = 0.f;
    #pragma unroll
    for (int t = 0; t < MTt; t++) { e[t] = __expf(e[t] - mx); ssum += e[t]; }
    float inv = (1.f / (float)Mm) / ssum;
    *(float4*)(dstRow)     = make_float4(e[0]*inv, e[1]*inv, e[2]*inv, e[3]*inv);
    *(float4*)(dstRow + 4) = make_float4(e[4]*inv, e[5]*inv, e[6]*inv, e[7]*inv);
    *(float2*)(dstRow + 8) = make_float2(e[8]*inv, e[9]*inv);
}

// ---------------------------------------------------------------------------
// Kernel 1: G = x @ F2^T (+ fused F2 row norms)
// ---------------------------------------------------------------------------
__global__ __launch_bounds__(256, 2)
void gemm_kernel(const float* __restrict__ x, const float* __restrict__ F2) {
    extern __shared__ float sm[];
    float* sF2 = sm;                 // 160 x 129
    float* sX  = sm + KT * 129;      // 40 x 128
    int tid = threadIdx.x;
    int r0 = blockIdx.x * GEMM_ROWS;

    for (int i = tid; i < KT * NF; i += 256) {
        int r = i >> 7, f = i & 127;
        sF2[r * 129 + f] = F2[i];
    }
    for (int i = tid; i < GEMM_ROWS * NF; i += 256)
        sX[i] = x[(size_t)r0 * NF + i];
    __syncthreads();

    if (blockIdx.x == 0 && tid >= 64 && tid < 64 + KT) {
        int r = tid - 64;
        float s = 0.f;
        #pragma unroll 8
        for (int f = 0; f < NF; f++) { float v = sF2[r * 129 + f]; s += v * v; }
        g_f2n[r] = s;
    }

    int tm = tid >> 5;
    int tn = tid & 31;
    float acc[5][5];
    #pragma unroll
    for (int i = 0; i < 5; i++)
        #pragma unroll
        for (int j = 0; j < 5; j++) acc[i][j] = 0.f;

    for (int f = 0; f < NF; f++) {
        float av[5], bv[5];
        #pragma unroll
        for (int i = 0; i < 5; i++) av[i] = sX[(tm * 5 + i) * NF + f];
        #pragma unroll
        for (int j = 0; j < 5; j++) bv[j] = sF2[(tn * 5 + j) * 129 + f];
        #pragma unroll
        for (int i = 0; i < 5; i++)
            #pragma unroll
            for (int j = 0; j < 5; j++) acc[i][j] += av[i] * bv[j];
    }
    #pragma unroll
    for (int i = 0; i < 5; i++) {
        int row = r0 + tm * 5 + i;
        #pragma unroll
        for (int j = 0; j < 5; j++)
            g_G[(size_t)row * KT + tn * 5 + j] = acc[i][j];
    }
}

// ---------------------------------------------------------------------------
// Kernel 2: barrier-free mirror-descent with shared u = C2 @ T0.
// y2^(m) = u + sum_{b in extras_m} C2 @ T[b]  (extras rare, guarded path).
// ---------------------------------------------------------------------------
struct SmemMain {
    float T  [NT * TKSTR];    // 16 regions x (17 rows x 12)
    float C2 [NT * MTt * PT]; // rows padded to 12, pads zero
    float q  [NT * PT];
    float cc [NT * PT];
    float u  [NT * PT];       // C2 @ T0 per template
    int   nbrs[Mm];
    int   dstl[Mm * DEG];
    unsigned mask[Mm];
};

__global__ __launch_bounds__(THREADS, 4)
void main_kernel(const int* __restrict__ dst, const float* __restrict__ C2g,
                 const float* __restrict__ alpha0, float* __restrict__ out) {
    extern __shared__ char smraw[];
    SmemMain& s = *reinterpret_cast<SmemMain*>(smraw);
    int n = blockIdx.x, tid = threadIdx.x;
    int w = tid >> 5, lane = tid & 31;
    int hf = lane >> 4, sub = lane & 15;
    int k = 2 * w + hf;
    int m = sub + 1;
    const float NEG_INF = __int_as_float(0xff800000);

    float a0 = alpha0[0];
    float alpha = 1.f / (1.f + __expf(-a0));
    float coefA = alpha * 10.f;
    float coefM = (1.f - alpha) * 10.f;
    float cA2 = 2.f * coefA, cA4 = 4.f * coefA;
    ull cA2p = pk2(cA2, cA2);
    ull ncA4p = pk2(-cA4, -cA4);
    ull neg1p = pk2(-1.f, -1.f);

    // --- prologue (parallel) ---
    if (tid < Mm) {
        s.nbrs[tid] = (tid == 0) ? n : dst[n * DEG + tid - 1];
        s.mask[tid] = 0u;
    }
    __syncthreads();
    for (int i = tid; i < Mm * DEG; i += THREADS)
        s.dstl[i] = dst[s.nbrs[i >> 4] * DEG + (i & 15)];
    for (int i = tid; i < NT * MTt * PT; i += THREADS) {
        int row = i / PT, col = i - row * PT;
        s.C2[i] = (col < MTt) ? C2g[row * MTt + col] : 0.f;
    }
    __syncthreads();
    for (int i = tid; i < Mm * Mm; i += THREADS) {
        int a = i / Mm, b = i - a * Mm;
        int me = s.nbrs[a], nb = s.nbrs[b];
        bool adj = false;
        #pragma unroll
        for (int j = 0; j < DEG; j++)
            adj = adj || (s.dstl[a * DEG + j] == nb) ||
                         (s.dstl[b * DEG + j] == me);
        if (adj) atomicOr(&s.mask[a], 1u << b);
    }
    __syncthreads();

    // --- per-thread persistent state ---
    float* Tk = &s.T[k * TKSTR];
    float* Trow = Tk + m * PT;
    unsigned extras = s.mask[m] & ~1u;   // bit 0 always set for m>=1
    bool diag0 = (s.mask[0] & 1u) != 0;

    ull ltp[5], McBp[5];
    float lt0, McB0;
    {
        // Only t-varying part of the cost (t-constant shifts cancel in softmax)
        const float* Grow = g_G + (size_t)s.nbrs[m] * KT + k * MTt;
        const float* f2p  = g_f2n + k * MTt;
        #pragma unroll
        for (int j = 0; j < 5; j++) {
            float a = coefM * (f2p[2*j]   - 2.f * __ldg(Grow + 2*j));
            float b = coefM * (f2p[2*j+1] - 2.f * __ldg(Grow + 2*j+1));
            McBp[j] = pk2(a, b);
            ltp[j] = 0ULL;
        }
        int t0i = (sub < MTt) ? sub : 9;
        McB0 = coefM * (f2p[t0i] - 2.f * __ldg(g_G + (size_t)n * KT + k * MTt + t0i));
        lt0 = (sub < MTt) ? 0.f : NEG_INF;
    }
    __syncthreads();   // last block barrier

    for (int it = 0; it <= NITER; it++) {
        // A) softmax rows 1..16 -> T rows; row 0 via half-warp shuffles
        softmax_store(ltp, Trow);
        {
            float mx0 = lt0;
            #pragma unroll
            for (int d = 1; d < 16; d <<= 1)
                mx0 = fmaxf(mx0, __shfl_xor_sync(0xffffffffu, mx0, d));
            float e0 = __expf(lt0 - mx0);
            float ss0 = e0;
            #pragma unroll
            for (int d = 1; d < 16; d <<= 1)
                ss0 += __shfl_xor_sync(0xffffffffu, ss0, d);
            if (sub < MTt) Tk[sub] = e0 * ((1.f / (float)Mm) / ss0);
        }
        __syncwarp();
        if (it == NITER) break;

        // B) q colsums (lanes sub<10, one column each)
        if (sub < MTt) {
            float acc = 0.f;
            #pragma unroll
            for (int mm = 0; mm < Mm; mm++) acc += Tk[mm * PT + sub];
            s.q[k * PT + sub] = acc;
        }
        __syncwarp();

        // C) lanes sub<10: cc[k][sub], u[k][sub] = (C2@T0)[sub], row-0 update
        if (sub < MTt) {
            ull qc[5], cr[5], t0c[5];
            ld_chunk(qc, &s.q[k * PT]);
            ld_chunk(cr, &s.C2[(k * MTt + sub) * PT]);
            ld_chunk(t0c, Tk);
            ull cacc = 0ULL, qacc = 0ULL, uacc = 0ULL;
            #pragma unroll
            for (int j = 0; j < 5; j++) {
                ull sq = mul2r(cr[j], cr[j]);
                ffma2(cacc, qc[j], sq);        // constC2 = q . C2^2[s]
                ffma2(qacc, qc[j], cr[j]);     // q . C2[s]
                ffma2(uacc, t0c[j], cr[j]);    // u[s] = T0 . C2[s]
            }
            float cc_s = hadd2(cacc);
            float u_s  = hadd2(uacc);
            float y20_s = hadd2(qacc) - (diag0 ? 0.f : u_s);  // y2 row 0
            s.cc[k * PT + sub] = cc_s;
            s.u [k * PT + sub] = u_s;
            lt0 -= (McB0 + cA2 * cc_s - cA4 * y20_s);
        }
        __syncwarp();

        // D) rows: y2 = u (+ rare extras deltas), then register update
        {
            ull ccp[5], y2p[5];
            ld_chunk(ccp, &s.cc[k * PT]);
            ld_chunk(y2p, &s.u[k * PT]);
            unsigned msk = extras;
            if (__any_sync(0xffffffffu, msk != 0u)) {
                while (msk) {
                    int b = __ffs(msk) - 1;
                    msk &= msk - 1;
                    ull tb[5];
                    ld_chunk(tb, Tk + b * PT);
                    float tv[10];
                    #pragma unroll
                    for (int j = 0; j < 5; j++) upk2(tv[2*j], tv[2*j+1], tb[j]);
                    #pragma unroll
                    for (int t = 0; t < MTt; t++) {
                        ull rp[5];
                        ld_chunk(rp, &s.C2[(k * MTt + t) * PT]);
                        ull yt = pk2(tv[t], tv[t]);
                        #pragma unroll
                        for (int j = 0; j < 5; j++) ffma2(y2p[j], yt, rp[j]);
                    }
                }
            }
            lt_update(ltp, McBp, ccp, y2p, cA2p, ncA4p, neg1p);
        }
    }

    // --- output marginals ---
    if (sub < MTt) {
        float acc = 0.f;
        #pragma unroll
        for (int mm = 0; mm < Mm; mm++) acc += Tk[mm * PT + sub];
        out[(size_t)n * KT + k * MTt + sub] = acc;
    }
}

// ---------------------------------------------------------------------------
extern "C" void kernel_launch(void* const* d_in, const int* in_sizes, int n_in,
                              void* d_out, int out_size) {
    const float* x   = (const float*)d_in[0];
    const int*   ei  = (const int*)d_in[1];
    const float* C2g = (const float*)d_in[2];
    const float* F2  = (const float*)d_in[3];
    const float* a0  = (const float*)d_in[4];
    float* out = (float*)d_out;
    const int* dst = ei + Nn * DEG;

    cudaFuncSetAttribute(gemm_kernel, cudaFuncAttributeMaxDynamicSharedMemorySize,
                         GEMM_SMEM);
    cudaFuncSetAttribute(main_kernel, cudaFuncAttributeMaxDynamicSharedMemorySize,
                         (int)sizeof(SmemMain));

    gemm_kernel<<<Nn / GEMM_ROWS, 256, GEMM_SMEM>>>(x, F2);
    main_kernel<<<Nn, THREADS, sizeof(SmemMain)>>>(dst, C2g, a0, out);
}

// round 14
// speedup vs baseline: 1.1240x; 1.1240x over previous
#include <cuda_runtime.h>

#define Nn    6000
#define DEG   16
#define Mm    17          // DEG + 1
#define NT    16
#define MTt   10
#define NF    128
#define KT    160         // NT * MTt
#define PT    12          // padded per-template chunk
#define TKSTR 204         // per-k T region stride (17 rows x 12)
#define NITER 10
#define THREADS 256       // 8 warps; warp w owns k = 2w, 2w+1
#define GEMM_ROWS 40
#define GEMM_SMEM ((KT * 129 + GEMM_ROWS * NF) * 4)

__device__ float g_G[Nn * KT];
__device__ float g_f2n[KT];

// ---------------------------------------------------------------------------
// packed f32x2 helpers (sm_103a)
// ---------------------------------------------------------------------------
typedef unsigned long long ull;
__device__ __forceinline__ ull pk2(float lo, float hi) {
    ull r;
    asm("mov.b64 %0, {%1, %2};" : "=l"(r) : "f"(lo), "f"(hi));
    return r;
}
__device__ __forceinline__ void upk2(float& lo, float& hi, ull v) {
    asm("mov.b64 {%0, %1}, %2;" : "=f"(lo), "=f"(hi) : "l"(v));
}
__device__ __forceinline__ void ffma2(ull& d, ull a, ull b) {
    asm("fma.rn.f32x2 %0, %1, %2, %0;" : "+l"(d) : "l"(a), "l"(b));
}
__device__ __forceinline__ ull fma2r(ull a, ull b, ull c) {
    ull d;
    asm("fma.rn.f32x2 %0, %1, %2, %3;" : "=l"(d) : "l"(a), "l"(b), "l"(c));
    return d;
}
__device__ __forceinline__ ull mul2r(ull a, ull b) {
    ull d;
    asm("mul.rn.f32x2 %0, %1, %2;" : "=l"(d) : "l"(a), "l"(b));
    return d;
}
__device__ __forceinline__ float hadd2(ull v) {
    float lo, hi; upk2(lo, hi, v);
    return lo + hi;
}
__device__ __forceinline__ void ld_chunk(ull* v, const float* p) {
    float4 a = *(const float4*)p, b = *(const float4*)(p + 4),
           c = *(const float4*)(p + 8);
    v[0] = pk2(a.x, a.y); v[1] = pk2(a.z, a.w);
    v[2] = pk2(b.x, b.y); v[3] = pk2(b.z, b.w);
    v[4] = pk2(c.x, c.y);
}
__device__ __forceinline__ void lt_update(ull* ltp, const ull* McBp,
                                          const ull* ccp, const ull* y2p,
                                          ull cA2p, ull ncA4p, ull neg1p) {
    #pragma unroll
    for (int j = 0; j < 5; j++) {
        ull d = fma2r(cA2p, ccp[j], McBp[j]);
        d = fma2r(ncA4p, y2p[j], d);
        ltp[j] = fma2r(d, neg1p, ltp[j]);
    }
}
// softmax over 10 packed values -> T row (scaled 1/17); stores 10 floats only
__device__ __forceinline__ void softmax_store(const ull* ltp, float* dstRow) {
    float e[10];
    #pragma unroll
    for (int j = 0; j < 5; j++) upk2(e[2*j], e[2*j+1], ltp[j]);
    float mx = e[0];
    #pragma unroll
    for (int t = 1; t < MTt; t++) mx = fmaxf(mx, e[t]);
    float ssum = 0.f;
    #pragma unroll
    for (int t = 0; t < MTt; t++) { e[t] = __expf(e[t] - mx); ssum += e[t]; }
    float inv = (1.f / (float)Mm) / ssum;
    *(float4*)(dstRow)     = make_float4(e[0]*inv, e[1]*inv, e[2]*inv, e[3]*inv);
    *(float4*)(dstRow + 4) = make_float4(e[4]*inv, e[5]*inv, e[6]*inv, e[7]*inv);
    *(float2*)(dstRow + 8) = make_float2(e[8]*inv, e[9]*inv);
}

// ---------------------------------------------------------------------------
// Kernel 1: G = x @ F2^T (+ fused F2 row norms)
// ---------------------------------------------------------------------------
__global__ __launch_bounds__(256, 2)
void gemm_kernel(const float* __restrict__ x, const float* __restrict__ F2) {
    extern __shared__ float sm[];
    float* sF2 = sm;                 // 160 x 129
    float* sX  = sm + KT * 129;      // 40 x 128
    int tid = threadIdx.x;
    int r0 = blockIdx.x * GEMM_ROWS;

    for (int i = tid; i < KT * NF; i += 256) {
        int r = i >> 7, f = i & 127;
        sF2[r * 129 + f] = F2[i];
    }
    for (int i = tid; i < GEMM_ROWS * NF; i += 256)
        sX[i] = x[(size_t)r0 * NF + i];
    __syncthreads();

    if (blockIdx.x == 0 && tid >= 64 && tid < 64 + KT) {
        int r = tid - 64;
        float s = 0.f;
        #pragma unroll 8
        for (int f = 0; f < NF; f++) { float v = sF2[r * 129 + f]; s += v * v; }
        g_f2n[r] = s;
    }

    int tm = tid >> 5;
    int tn = tid & 31;
    float acc[5][5];
    #pragma unroll
    for (int i = 0; i < 5; i++)
        #pragma unroll
        for (int j = 0; j < 5; j++) acc[i][j] = 0.f;

    for (int f = 0; f < NF; f++) {
        float av[5], bv[5];
        #pragma unroll
        for (int i = 0; i < 5; i++) av[i] = sX[(tm * 5 + i) * NF + f];
        #pragma unroll
        for (int j = 0; j < 5; j++) bv[j] = sF2[(tn * 5 + j) * 129 + f];
        #pragma unroll
        for (int i = 0; i < 5; i++)
            #pragma unroll
            for (int j = 0; j < 5; j++) acc[i][j] += av[i] * bv[j];
    }
    #pragma unroll
    for (int i = 0; i < 5; i++) {
        int row = r0 + tm * 5 + i;
        #pragma unroll
        for (int j = 0; j < 5; j++)
            g_G[(size_t)row * KT + tn * 5 + j] = acc[i][j];
    }
}

// ---------------------------------------------------------------------------
// Kernel 2: barrier-free mirror-descent with shared u = C2 @ T0.
// y2^(m) = u + sum_{b in extras_m} C2 @ T[b]  (extras rare, guarded path).
// 3 blocks/SM (84-reg budget) — the 64-reg cap caused local-memory spills.
// ---------------------------------------------------------------------------
struct SmemMain {
    float T  [NT * TKSTR];    // 16 regions x (17 rows x 12)
    float C2 [NT * MTt * PT]; // rows padded to 12, pads zero
    float q  [NT * PT];
    float cc [NT * PT];
    float u  [NT * PT];       // C2 @ T0 per template
    int   nbrs[Mm];
    int   dstl[Mm * DEG];
    unsigned mask[Mm];
};

__global__ __launch_bounds__(THREADS, 3)
void main_kernel(const int* __restrict__ dst, const float* __restrict__ C2g,
                 const float* __restrict__ alpha0, float* __restrict__ out) {
    extern __shared__ char smraw[];
    SmemMain& s = *reinterpret_cast<SmemMain*>(smraw);
    int n = blockIdx.x, tid = threadIdx.x;
    int w = tid >> 5, lane = tid & 31;
    int hf = lane >> 4, sub = lane & 15;
    int k = 2 * w + hf;
    int m = sub + 1;
    const float NEG_INF = __int_as_float(0xff800000);

    float a0 = alpha0[0];
    float alpha = 1.f / (1.f + __expf(-a0));
    float coefA = alpha * 10.f;
    float coefM = (1.f - alpha) * 10.f;
    float cA2 = 2.f * coefA, cA4 = 4.f * coefA;
    ull cA2p = pk2(cA2, cA2);
    ull ncA4p = pk2(-cA4, -cA4);
    ull neg1p = pk2(-1.f, -1.f);

    // --- prologue (parallel) ---
    if (tid < Mm) {
        s.nbrs[tid] = (tid == 0) ? n : dst[n * DEG + tid - 1];
        s.mask[tid] = 0u;
    }
    __syncthreads();
    for (int i = tid; i < Mm * DEG; i += THREADS)
        s.dstl[i] = dst[s.nbrs[i >> 4] * DEG + (i & 15)];
    for (int i = tid; i < NT * MTt * PT; i += THREADS) {
        int row = i / PT, col = i - row * PT;
        s.C2[i] = (col < MTt) ? C2g[row * MTt + col] : 0.f;
    }
    __syncthreads();
    for (int i = tid; i < Mm * Mm; i += THREADS) {
        int a = i / Mm, b = i - a * Mm;
        int me = s.nbrs[a], nb = s.nbrs[b];
        bool adj = false;
        #pragma unroll
        for (int j = 0; j < DEG; j++)
            adj = adj || (s.dstl[a * DEG + j] == nb) ||
                         (s.dstl[b * DEG + j] == me);
        if (adj) atomicOr(&s.mask[a], 1u << b);
    }
    __syncthreads();

    // --- per-thread persistent state ---
    float* Tk = &s.T[k * TKSTR];
    float* Trow = Tk + m * PT;
    unsigned extras = s.mask[m] & ~1u;   // bit 0 always set for m>=1
    bool diag0 = (s.mask[0] & 1u) != 0;

    ull ltp[5], McBp[5];
    float lt0, McB0;
    {
        // Only t-varying part of the cost (t-constant shifts cancel in softmax)
        const float* Grow = g_G + (size_t)s.nbrs[m] * KT + k * MTt;
        const float* f2p  = g_f2n + k * MTt;
        #pragma unroll
        for (int j = 0; j < 5; j++) {
            float a = coefM * (f2p[2*j]   - 2.f * __ldg(Grow + 2*j));
            float b = coefM * (f2p[2*j+1] - 2.f * __ldg(Grow + 2*j+1));
            McBp[j] = pk2(a, b);
            ltp[j] = 0ULL;
        }
        int t0i = (sub < MTt) ? sub : 9;
        McB0 = coefM * (f2p[t0i] - 2.f * __ldg(g_G + (size_t)n * KT + k * MTt + t0i));
        lt0 = (sub < MTt) ? 0.f : NEG_INF;
    }
    __syncthreads();   // last block barrier

    for (int it = 0; it <= NITER; it++) {
        // A) softmax rows 1..16 -> T rows; row 0 via half-warp shuffles
        softmax_store(ltp, Trow);
        {
            float mx0 = lt0;
            #pragma unroll
            for (int d = 1; d < 16; d <<= 1)
                mx0 = fmaxf(mx0, __shfl_xor_sync(0xffffffffu, mx0, d));
            float e0 = __expf(lt0 - mx0);
            float ss0 = e0;
            #pragma unroll
            for (int d = 1; d < 16; d <<= 1)
                ss0 += __shfl_xor_sync(0xffffffffu, ss0, d);
            if (sub < MTt) Tk[sub] = e0 * ((1.f / (float)Mm) / ss0);
        }
        __syncwarp();
        if (it == NITER) break;

        // B) q colsums (lanes sub<10, one column each)
        if (sub < MTt) {
            float acc = 0.f;
            #pragma unroll
            for (int mm = 0; mm < Mm; mm++) acc += Tk[mm * PT + sub];
            s.q[k * PT + sub] = acc;
        }
        __syncwarp();

        // C) lanes sub<10: cc[k][sub], u[k][sub] = (C2@T0)[sub], row-0 update
        if (sub < MTt) {
            ull qc[5], cr[5], t0c[5];
            ld_chunk(qc, &s.q[k * PT]);
            ld_chunk(cr, &s.C2[(k * MTt + sub) * PT]);
            ld_chunk(t0c, Tk);
            ull cacc = 0ULL, qacc = 0ULL, uacc = 0ULL;
            #pragma unroll
            for (int j = 0; j < 5; j++) {
                ull sq = mul2r(cr[j], cr[j]);
                ffma2(cacc, qc[j], sq);        // constC2 = q . C2^2[s]
                ffma2(qacc, qc[j], cr[j]);     // q . C2[s]
                ffma2(uacc, t0c[j], cr[j]);    // u[s] = T0 . C2[s]
            }
            float cc_s = hadd2(cacc);
            float u_s  = hadd2(uacc);
            float y20_s = hadd2(qacc) - (diag0 ? 0.f : u_s);  // y2 row 0
            s.cc[k * PT + sub] = cc_s;
            s.u [k * PT + sub] = u_s;
            lt0 -= (McB0 + cA2 * cc_s - cA4 * y20_s);
        }
        __syncwarp();

        // D) rows: y2 = u (+ rare extras deltas), then register update
        {
            ull ccp[5], y2p[5];
            ld_chunk(ccp, &s.cc[k * PT]);
            ld_chunk(y2p, &s.u[k * PT]);
            unsigned msk = extras;
            if (__any_sync(0xffffffffu, msk != 0u)) {
                while (msk) {
                    int b = __ffs(msk) - 1;
                    msk &= msk - 1;
                    ull tb[5];
                    ld_chunk(tb, Tk + b * PT);
                    float tv[10];
                    #pragma unroll
                    for (int j = 0; j < 5; j++) upk2(tv[2*j], tv[2*j+1], tb[j]);
                    #pragma unroll
                    for (int t = 0; t < MTt; t++) {
                        ull rp[5];
                        ld_chunk(rp, &s.C2[(k * MTt + t) * PT]);
                        ull yt = pk2(tv[t], tv[t]);
                        #pragma unroll
                        for (int j = 0; j < 5; j++) ffma2(y2p[j], yt, rp[j]);
                    }
                }
            }
            lt_update(ltp, McBp, ccp, y2p, cA2p, ncA4p, neg1p);
        }
    }

    // --- output marginals ---
    if (sub < MTt) {
        float acc = 0.f;
        #pragma unroll
        for (int mm = 0; mm < Mm; mm++) acc += Tk[mm * PT + sub];
        out[(size_t)n * KT + k * MTt + sub] = acc;
    }
}

// ---------------------------------------------------------------------------
extern "C" void kernel_launch(void* const* d_in, const int* in_sizes, int n_in,
                              void* d_out, int out_size) {
    const float* x   = (const float*)d_in[0];
    const int*   ei  = (const int*)d_in[1];
    const float* C2g = (const float*)d_in[2];
    const float* F2  = (const float*)d_in[3];
    const float* a0  = (const float*)d_in[4];
    float* out = (float*)d_out;
    const int* dst = ei + Nn * DEG;

    cudaFuncSetAttribute(gemm_kernel, cudaFuncAttributeMaxDynamicSharedMemorySize,
                         GEMM_SMEM);
    cudaFuncSetAttribute(main_kernel, cudaFuncAttributeMaxDynamicSharedMemorySize,
                         (int)sizeof(SmemMain));

    gemm_kernel<<<Nn / GEMM_ROWS, 256, GEMM_SMEM>>>(x, F2);
    main_kernel<<<Nn, THREADS, sizeof(SmemMain)>>>(dst, C2g, a0, out);
}

// round 16
// speedup vs baseline: 2.6153x; 2.3267x over previous
#include <cuda_runtime.h>

#define Nn    6000
#define DEG   16
#define Mm    17          // DEG + 1
#define NT    16
#define MTt   10
#define NF    128
#define KT    160         // NT * MTt
#define PT    12          // padded per-template chunk
#define TKSTR 204         // per-k T region stride (17 rows x 12)
#define NITER 10
#define THREADS 256       // 8 warps; warp w owns k = 2w, 2w+1
#define GEMM_ROWS 40
#define GEMM_SMEM ((KT * 129 + GEMM_ROWS * NF) * 4)

__device__ float g_G[Nn * KT];
__device__ float g_f2n[KT];

// ---------------------------------------------------------------------------
// packed f32x2 helpers (sm_103a)
// ---------------------------------------------------------------------------
typedef unsigned long long ull;
__device__ __forceinline__ ull pk2(float lo, float hi) {
    ull r;
    asm("mov.b64 %0, {%1, %2};" : "=l"(r) : "f"(lo), "f"(hi));
    return r;
}
__device__ __forceinline__ void upk2(float& lo, float& hi, ull v) {
    asm("mov.b64 {%0, %1}, %2;" : "=f"(lo), "=f"(hi) : "l"(v));
}
__device__ __forceinline__ void ffma2(ull& d, ull a, ull b) {
    asm("fma.rn.f32x2 %0, %1, %2, %0;" : "+l"(d) : "l"(a), "l"(b));
}
__device__ __forceinline__ ull fma2r(ull a, ull b, ull c) {
    ull d;
    asm("fma.rn.f32x2 %0, %1, %2, %3;" : "=l"(d) : "l"(a), "l"(b), "l"(c));
    return d;
}
__device__ __forceinline__ ull mul2r(ull a, ull b) {
    ull d;
    asm("mul.rn.f32x2 %0, %1, %2;" : "=l"(d) : "l"(a), "l"(b));
    return d;
}
__device__ __forceinline__ void add2(ull& d, ull a) {
    asm("add.rn.f32x2 %0, %0, %1;" : "+l"(d) : "l"(a));
}
__device__ __forceinline__ float hadd2(ull v) {
    float lo, hi; upk2(lo, hi, v);
    return lo + hi;
}
__device__ __forceinline__ void ld_chunk(ull* v, const float* p) {
    float4 a = *(const float4*)p, b = *(const float4*)(p + 4),
           c = *(const float4*)(p + 8);
    v[0] = pk2(a.x, a.y); v[1] = pk2(a.z, a.w);
    v[2] = pk2(b.x, b.y); v[3] = pk2(b.z, b.w);
    v[4] = pk2(c.x, c.y);
}
__device__ __forceinline__ void lt_update(ull* ltp, const ull* McBp,
                                          const ull* ccp, const ull* y2p,
                                          ull cA2p, ull ncA4p, ull neg1p) {
    #pragma unroll
    for (int j = 0; j < 5; j++) {
        ull d = fma2r(cA2p, ccp[j], McBp[j]);
        d = fma2r(ncA4p, y2p[j], d);
        ltp[j] = fma2r(d, neg1p, ltp[j]);
    }
}
// softmax over 10 packed values -> T row (scaled 1/17); stores 10 floats only
__device__ __forceinline__ void softmax_store(const ull* ltp, float* dstRow) {
    float e[10];
    #pragma unroll
    for (int j = 0; j < 5; j++) upk2(e[2*j], e[2*j+1], ltp[j]);
    float mx = e[0];
    #pragma unroll
    for (int t = 1; t < MTt; t++) mx = fmaxf(mx, e[t]);
    float ssum = 0.f;
    #pragma unroll
    for (int t = 0; t < MTt; t++) { e[t] = __expf(e[t] - mx); ssum += e[t]; }
    float inv = (1.f / (float)Mm) / ssum;
    *(float4*)(dstRow)     = make_float4(e[0]*inv, e[1]*inv, e[2]*inv, e[3]*inv);
    *(float4*)(dstRow + 4) = make_float4(e[4]*inv, e[5]*inv, e[6]*inv, e[7]*inv);
    *(float2*)(dstRow + 8) = make_float2(e[8]*inv, e[9]*inv);
}

// ---------------------------------------------------------------------------
// Kernel 1: G = x @ F2^T (+ fused F2 row norms)
// ---------------------------------------------------------------------------
__global__ __launch_bounds__(256, 2)
void gemm_kernel(const float* __restrict__ x, const float* __restrict__ F2) {
    extern __shared__ float sm[];
    float* sF2 = sm;                 // 160 x 129
    float* sX  = sm + KT * 129;      // 40 x 128
    int tid = threadIdx.x;
    int r0 = blockIdx.x * GEMM_ROWS;

    for (int i = tid; i < KT * NF; i += 256) {
        int r = i >> 7, f = i & 127;
        sF2[r * 129 + f] = F2[i];
    }
    for (int i = tid; i < GEMM_ROWS * NF; i += 256)
        sX[i] = x[(size_t)r0 * NF + i];
    __syncthreads();

    if (blockIdx.x == 0 && tid >= 64 && tid < 64 + KT) {
        int r = tid - 64;
        float s = 0.f;
        #pragma unroll 8
        for (int f = 0; f < NF; f++) { float v = sF2[r * 129 + f]; s += v * v; }
        g_f2n[r] = s;
    }

    int tm = tid >> 5;
    int tn = tid & 31;
    float acc[5][5];
    #pragma unroll
    for (int i = 0; i < 5; i++)
        #pragma unroll
        for (int j = 0; j < 5; j++) acc[i][j] = 0.f;

    for (int f = 0; f < NF; f++) {
        float av[5], bv[5];
        #pragma unroll
        for (int i = 0; i < 5; i++) av[i] = sX[(tm * 5 + i) * NF + f];
        #pragma unroll
        for (int j = 0; j < 5; j++) bv[j] = sF2[(tn * 5 + j) * 129 + f];
        #pragma unroll
        for (int i = 0; i < 5; i++)
            #pragma unroll
            for (int j = 0; j < 5; j++) acc[i][j] += av[i] * bv[j];
    }
    #pragma unroll
    for (int i = 0; i < 5; i++) {
        int row = r0 + tm * 5 + i;
        #pragma unroll
        for (int j = 0; j < 5; j++)
            g_G[(size_t)row * KT + tn * 5 + j] = acc[i][j];
    }
}

// ---------------------------------------------------------------------------
// Kernel 2: barrier-free mirror-descent, hybrid y2 path:
//  fast path (warp has NO extra nbr-nbr edges): y2 = u = C2 @ T0 (shared)
//  slow path: round-12 dense gather + matvec in stage B (register-proven)
// ---------------------------------------------------------------------------
struct SmemMain {
    float T  [NT * TKSTR];    // 16 regions x (17 rows x 12)
    float C2 [NT * MTt * PT]; // rows padded to 12, pads zero
    float q  [NT * PT];
    float cc [NT * PT];
    float u  [NT * PT];       // C2 @ T0 per template
    int   nbrs[Mm];
    int   dstl[Mm * DEG];
    unsigned mask[Mm];
};

__global__ __launch_bounds__(THREADS, 3)
void main_kernel(const int* __restrict__ dst, const float* __restrict__ C2g,
                 const float* __restrict__ alpha0, float* __restrict__ out) {
    extern __shared__ char smraw[];
    SmemMain& s = *reinterpret_cast<SmemMain*>(smraw);
    int n = blockIdx.x, tid = threadIdx.x;
    int w = tid >> 5, lane = tid & 31;
    int hf = lane >> 4, sub = lane & 15;
    int k = 2 * w + hf;
    int m = sub + 1;
    const float NEG_INF = __int_as_float(0xff800000);

    float a0 = alpha0[0];
    float alpha = 1.f / (1.f + __expf(-a0));
    float coefA = alpha * 10.f;
    float coefM = (1.f - alpha) * 10.f;
    float cA2 = 2.f * coefA, cA4 = 4.f * coefA;
    ull cA2p = pk2(cA2, cA2);
    ull ncA4p = pk2(-cA4, -cA4);
    ull neg1p = pk2(-1.f, -1.f);

    // --- prologue (parallel) ---
    if (tid < Mm) {
        s.nbrs[tid] = (tid == 0) ? n : dst[n * DEG + tid - 1];
        s.mask[tid] = 0u;
    }
    __syncthreads();
    for (int i = tid; i < Mm * DEG; i += THREADS)
        s.dstl[i] = dst[s.nbrs[i >> 4] * DEG + (i & 15)];
    for (int i = tid; i < NT * MTt * PT; i += THREADS) {
        int row = i / PT, col = i - row * PT;
        s.C2[i] = (col < MTt) ? C2g[row * MTt + col] : 0.f;
    }
    __syncthreads();
    for (int i = tid; i < Mm * Mm; i += THREADS) {
        int a = i / Mm, b = i - a * Mm;
        int me = s.nbrs[a], nb = s.nbrs[b];
        bool adj = false;
        #pragma unroll
        for (int j = 0; j < DEG; j++)
            adj = adj || (s.dstl[a * DEG + j] == nb) ||
                         (s.dstl[b * DEG + j] == me);
        if (adj) atomicOr(&s.mask[a], 1u << b);
    }
    __syncthreads();

    // --- per-thread persistent state ---
    float* Tk = &s.T[k * TKSTR];
    float* Trow = Tk + m * PT;
    unsigned extras = s.mask[m] & ~1u;   // bit 0 always set for m>=1
    bool diag0 = (s.mask[0] & 1u) != 0;
    // warp-uniform: any lane (any row of this node) with an extra nbr-nbr edge?
    bool warpExtras = __any_sync(0xffffffffu, extras != 0u);

    ull ltp[5], McBp[5];
    float lt0, McB0;
    {
        // Only t-varying part of the cost (t-constant shifts cancel in softmax)
        const float* Grow = g_G + (size_t)s.nbrs[m] * KT + k * MTt;
        const float* f2p  = g_f2n + k * MTt;
        #pragma unroll
        for (int j = 0; j < 5; j++) {
            float a = coefM * (f2p[2*j]   - 2.f * __ldg(Grow + 2*j));
            float b = coefM * (f2p[2*j+1] - 2.f * __ldg(Grow + 2*j+1));
            McBp[j] = pk2(a, b);
            ltp[j] = 0ULL;
        }
        int t0i = (sub < MTt) ? sub : 9;
        McB0 = coefM * (f2p[t0i] - 2.f * __ldg(g_G + (size_t)n * KT + k * MTt + t0i));
        lt0 = (sub < MTt) ? 0.f : NEG_INF;
    }
    __syncthreads();   // last block barrier

    for (int it = 0; it <= NITER; it++) {
        // A) softmax rows 1..16 -> T rows; row 0 via half-warp shuffles
        softmax_store(ltp, Trow);
        {
            float mx0 = lt0;
            #pragma unroll
            for (int d = 1; d < 16; d <<= 1)
                mx0 = fmaxf(mx0, __shfl_xor_sync(0xffffffffu, mx0, d));
            float e0 = __expf(lt0 - mx0);
            float ss0 = e0;
            #pragma unroll
            for (int d = 1; d < 16; d <<= 1)
                ss0 += __shfl_xor_sync(0xffffffffu, ss0, d);
            if (sub < MTt) Tk[sub] = e0 * ((1.f / (float)Mm) / ss0);
        }
        __syncwarp();
        if (it == NITER) break;

        // B) q colsums (lanes sub<10); slow path: dense gather + matvec
        if (sub < MTt) {
            float acc = 0.f;
            #pragma unroll
            for (int mm = 0; mm < Mm; mm++) acc += Tk[mm * PT + sub];
            s.q[k * PT + sub] = acc;
        }
        ull y2p[5];
        #pragma unroll
        for (int j = 0; j < 5; j++) y2p[j] = 0ULL;
        if (warpExtras) {
            // y1 = T0 + extras, then dense y2 = C2 @ y1 (round-12 proven path)
            ull y1p[5];
            ld_chunk(y1p, Tk);
            unsigned msk = extras;
            while (msk) {
                int b = __ffs(msk) - 1;
                msk &= msk - 1;
                ull ex[5];
                ld_chunk(ex, Tk + b * PT);
                #pragma unroll
                for (int j = 0; j < 5; j++) add2(y1p[j], ex[j]);
            }
            float y[10];
            #pragma unroll
            for (int j = 0; j < 5; j++) upk2(y[2*j], y[2*j+1], y1p[j]);
            #pragma unroll
            for (int t = 0; t < MTt; t++) {
                ull rp[5];
                ld_chunk(rp, &s.C2[(k * MTt + t) * PT]);
                ull yt = pk2(y[t], y[t]);
                #pragma unroll
                for (int j = 0; j < 5; j++) ffma2(y2p[j], yt, rp[j]);
            }
        }
        __syncwarp();

        // C) lanes sub<10: cc[k][sub], u[k][sub] = (C2@T0)[sub], row-0 update
        if (sub < MTt) {
            ull qc[5], cr[5], t0c[5];
            ld_chunk(qc, &s.q[k * PT]);
            ld_chunk(cr, &s.C2[(k * MTt + sub) * PT]);
            ld_chunk(t0c, Tk);
            ull cacc = 0ULL, qacc = 0ULL, uacc = 0ULL;
            #pragma unroll
            for (int j = 0; j < 5; j++) {
                ull sq = mul2r(cr[j], cr[j]);
                ffma2(cacc, qc[j], sq);        // constC2 = q . C2^2[s]
                ffma2(qacc, qc[j], cr[j]);     // q . C2[s]
                ffma2(uacc, t0c[j], cr[j]);    // u[s] = T0 . C2[s]
            }
            float cc_s = hadd2(cacc);
            float u_s  = hadd2(uacc);
            float y20_s = hadd2(qacc) - (diag0 ? 0.f : u_s);  // y2 row 0
            s.cc[k * PT + sub] = cc_s;
            s.u [k * PT + sub] = u_s;
            lt0 -= (McB0 + cA2 * cc_s - cA4 * y20_s);
        }
        __syncwarp();

        // D) fast path reads y2 = u; then register update
        {
            ull ccp[5];
            ld_chunk(ccp, &s.cc[k * PT]);
            if (!warpExtras)
                ld_chunk(y2p, &s.u[k * PT]);
            lt_update(ltp, McBp, ccp, y2p, cA2p, ncA4p, neg1p);
        }
    }

    // --- output marginals ---
    if (sub < MTt) {
        float acc = 0.f;
        #pragma unroll
        for (int mm = 0; mm < Mm; mm++) acc += Tk[mm * PT + sub];
        out[(size_t)n * KT + k * MTt + sub] = acc;
    }
}

// ---------------------------------------------------------------------------
extern "C" void kernel_launch(void* const* d_in, const int* in_sizes, int n_in,
                              void* d_out, int out_size) {
    const float* x   = (const float*)d_in[0];
    const int*   ei  = (const int*)d_in[1];
    const float* C2g = (const float*)d_in[2];
    const float* F2  = (const float*)d_in[3];
    const float* a0  = (const float*)d_in[4];
    float* out = (float*)d_out;
    const int* dst = ei + Nn * DEG;

    cudaFuncSetAttribute(gemm_kernel, cudaFuncAttributeMaxDynamicSharedMemorySize,
                         GEMM_SMEM);
    cudaFuncSetAttribute(main_kernel, cudaFuncAttributeMaxDynamicSharedMemorySize,
                         (int)sizeof(SmemMain));

    gemm_kernel<<<Nn / GEMM_ROWS, 256, GEMM_SMEM>>>(x, F2);
    main_kernel<<<Nn, THREADS, sizeof(SmemMain)>>>(dst, C2g, a0, out);
}